// round 14
// baseline (speedup 1.0000x reference)
#include <cuda_runtime.h>
#include <cuda_fp16.h>
#include <cstdint>

// ===================== problem constants =====================
#define U_DIM   14336
#define K_DIM   4096
#define NB      32
#define TILE_M  128
#define NCTA_U  (U_DIM / TILE_M)     // 112
#define NCHUNK  (K_DIM / 64)         // 64 chunks of 64 k-values
#define NSPLIT  4
#define NCHUNK_Q (NCHUNK / NSPLIT)   // 16 chunks per CTA
#define CLIPV   100.0f
// PRMT LUT bytes: crumb 0->0x00, 1->0x3C (+1 fp16 hi), 2->0xBC (-1), 3->0x00
#define HI_LUT  0x00BC3C00u

// smem geometry: fp16 B ring [n][k], 128B data + 16B pad per row
#define BROWN   144
#define B16BUF  (32 * BROWN)         // 4608 B per fp16 ring slot

// split-K fp32 partials: [split][n][u]; per-u-tile completion counters
__device__ float    g_part[NSPLIT * NB * U_DIM];
__device__ unsigned g_cnt[NCTA_U];

// ===================== helpers =====================
__device__ __forceinline__ uint32_t prmt(uint32_t a, uint32_t b, uint32_t s) {
    uint32_t r; asm("prmt.b32 %0,%1,%2,%3;" : "=r"(r) : "r"(a), "r"(b), "r"(s)); return r;
}
__device__ __forceinline__ uint32_t smem_u32(const void* p) {
    uint32_t a;
    asm("{ .reg .u64 t; cvta.to.shared.u64 t, %1; cvt.u32.u64 %0, t; }" : "=r"(a) : "l"(p));
    return a;
}
// merge 4 int32 (one crumb-byte each, low byte) -> one 32-bit word of 16 crumbs
__device__ __forceinline__ uint32_t mergew(uint4 q) {
    return prmt(prmt(q.x, q.y, 0x0040), prmt(q.z, q.w, 0x0040), 0x5410);
}
// decode: from 16-crumb word w, lane's quad q (sh=4q): crumbs (2q,2q+1) -> lo,
// crumbs (2q+8,2q+9) -> hi, as fp16x2
__device__ __forceinline__ void dec(uint32_t w, uint32_t sh, uint32_t& lo, uint32_t& hi) {
    uint32_t t   = w >> sh;
    uint32_t x   = t & 0x000F000Fu;
    uint32_t z   = x | (x << 2);
    uint32_t sel = (z & 0x33u) | ((z >> 8) & 0x3300u);
    uint32_t h   = prmt(HI_LUT, 0u, sel);
    lo = prmt(h, 0u, 0x1404u);
    hi = prmt(h, 0u, 0x3424u);
}
__device__ __forceinline__ void mma16816(float* c,
        uint32_t a0, uint32_t a1, uint32_t a2, uint32_t a3,
        uint32_t b0, uint32_t b1) {
    asm volatile(
        "mma.sync.aligned.m16n8k16.row.col.f32.f16.f16.f32 "
        "{%0,%1,%2,%3},{%4,%5,%6,%7},{%8,%9},{%0,%1,%2,%3};"
        : "+f"(c[0]), "+f"(c[1]), "+f"(c[2]), "+f"(c[3])
        : "r"(a0), "r"(a1), "r"(a2), "r"(a3), "r"(b0), "r"(b1));
}
// NON-transposed ldmatrix: B stored [n][k] fp16; 8 n-rows x 16B k-segment per matrix
__device__ __forceinline__ void ldsm4_nt(uint32_t addr,
        uint32_t& r0, uint32_t& r1, uint32_t& r2, uint32_t& r3) {
    asm volatile("ldmatrix.sync.aligned.m8n8.x4.shared.b16 {%0,%1,%2,%3}, [%4];"
        : "=r"(r0), "=r"(r1), "=r"(r2), "=r"(r3) : "r"(addr));
}
// pack 2 fp32 -> fp16x2 {lo, hi}
__device__ __forceinline__ uint32_t f16x2(float lo, float hi) {
    uint32_t r; asm("cvt.rn.f16x2.f32 %0, %1, %2;" : "=r"(r) : "f"(hi), "f"(lo)); return r;
}

// ===================== fused kernel =====================
// grid 448 x 128 threads, occupancy 4 (one wave on 148 SMs)
// CTA = (u-tile bu, K-quarter sq). B staged by direct LDG of x (L2-resident),
// in-register fp32->fp16 convert, STS into a 2-slot fp16 ring.
// Split-K reduce fused via per-tile atomic counter.
__global__ void __launch_bounds__(128, 4)
ternary_fused_kernel(const float* __restrict__ x,
                     const int*   __restrict__ pw,
                     const float* __restrict__ scale,
                     const float* __restrict__ bias,
                     float*       __restrict__ out) {
    __shared__ __align__(16) uint8_t sB16[2][B16BUF]; // fp16 B ring [n][k] (9216 B)
    __shared__ __align__(16) uint4   sW[4][32];       // per-warp W transpose (2048 B)
    __shared__ int sLast;

    const int tid  = threadIdx.x;
    const int lane = tid & 31;
    const int wid  = tid >> 5;
    const int bu   = blockIdx.x >> 2;        // u-tile    (0..111)
    const int sq   = blockIdx.x & 3;         // K-quarter (0..3)
    const int u0   = bu * TILE_M;
    const int c0   = sq * NCHUNK_Q;
    const int cEnd = c0 + NCHUNK_Q;
    const uint32_t sh = (lane & 3) * 4;
    const int rb   = lane >> 2;

    // ---- pw stream: lane owns weight row u0 + wid*32 + lane ----
    const int urow = u0 + wid * 32 + lane;
    const uint4* pwq = reinterpret_cast<const uint4*>(pw + (size_t)urow * (K_DIM / 4));

    const uint32_t sB0 = smem_u32(sB16);
    // B staging task: thread t -> n-row = t>>2, 16-float segment = t&3
    const int st_n = tid >> 2;
    const int st_s = tid & 3;
    const float* xrow = x + (size_t)st_n * K_DIM + st_s * 16;
    uint8_t* stb = reinterpret_cast<uint8_t*>(sB16) + st_n * BROWN + st_s * 32;
    // ldmatrix per-lane offset within a (ntile-pair, ks) call
    const uint32_t nb_off = (uint32_t)(((lane >> 4) & 1) * (8 * BROWN)
                                       + (lane & 7) * BROWN
                                       + ((lane >> 3) & 1) * 16);

    float acc[2][4][4];
#pragma unroll
    for (int a = 0; a < 2; ++a)
#pragma unroll
        for (int t = 0; t < 4; ++t)
#pragma unroll
            for (int j = 0; j < 4; ++j) acc[a][t][j] = 0.0f;

    // ---- prologue ----
    uint4 raw[2][4];
#pragma unroll
    for (int s = 0; s < 2; ++s)
#pragma unroll
        for (int i = 0; i < 4; ++i) raw[s][i] = pwq[(c0 + s) * 4 + i];

    // stage chunk c0 -> fp16 slot 0 (via regs), prefetch chunk c0+1 into regs
    float4 bx0, bx1, bx2, bx3;
    {
        const float* g = xrow + c0 * 64;
        bx0 = *reinterpret_cast<const float4*>(g);
        bx1 = *reinterpret_cast<const float4*>(g + 4);
        bx2 = *reinterpret_cast<const float4*>(g + 8);
        bx3 = *reinterpret_cast<const float4*>(g + 12);
        uint4 o0, o1;
        o0.x = f16x2(bx0.x, bx0.y); o0.y = f16x2(bx0.z, bx0.w);
        o0.z = f16x2(bx1.x, bx1.y); o0.w = f16x2(bx1.z, bx1.w);
        o1.x = f16x2(bx2.x, bx2.y); o1.y = f16x2(bx2.z, bx2.w);
        o1.z = f16x2(bx3.x, bx3.y); o1.w = f16x2(bx3.z, bx3.w);
        *reinterpret_cast<uint4*>(stb)      = o0;
        *reinterpret_cast<uint4*>(stb + 16) = o1;
        const float* g1 = xrow + (c0 + 1) * 64;
        bx0 = *reinterpret_cast<const float4*>(g1);
        bx1 = *reinterpret_cast<const float4*>(g1 + 4);
        bx2 = *reinterpret_cast<const float4*>(g1 + 8);
        bx3 = *reinterpret_cast<const float4*>(g1 + 12);
    }

    // ---- main loop: one __syncthreads per chunk ----
#pragma unroll 4
    for (int c = c0; c < cEnd; ++c) {
        // barrier: slot c&1 (written last iter / prologue) visible to all warps;
        // previous readers of slot (c+1)&1 (iter c-1) are done
        __syncthreads();

        // stage chunk c+1 from regs -> fp16 slot (c+1)&1; prefetch chunk c+2
        if (c + 1 < cEnd) {
            uint4 o0, o1;
            o0.x = f16x2(bx0.x, bx0.y); o0.y = f16x2(bx0.z, bx0.w);
            o0.z = f16x2(bx1.x, bx1.y); o0.w = f16x2(bx1.z, bx1.w);
            o1.x = f16x2(bx2.x, bx2.y); o1.y = f16x2(bx2.z, bx2.w);
            o1.z = f16x2(bx3.x, bx3.y); o1.w = f16x2(bx3.z, bx3.w);
            uint8_t* dst = stb + ((c + 1) & 1) * B16BUF;
            *reinterpret_cast<uint4*>(dst)      = o0;
            *reinterpret_cast<uint4*>(dst + 16) = o1;
            const int nc = (c + 2 < cEnd) ? (c + 2) : (cEnd - 1);
            const float* g = xrow + nc * 64;
            bx0 = *reinterpret_cast<const float4*>(g);
            bx1 = *reinterpret_cast<const float4*>(g + 4);
            bx2 = *reinterpret_cast<const float4*>(g + 8);
            bx3 = *reinterpret_cast<const float4*>(g + 12);
        }

        // W: merge chunk c, prefetch pw c+2, warp-local transpose via smem
        const int s = c & 1;
        {
            uint4 wv;
            wv.x = mergew(raw[s][0]);
            wv.y = mergew(raw[s][1]);
            wv.z = mergew(raw[s][2]);
            wv.w = mergew(raw[s][3]);
            int pc = (c + 2 < cEnd) ? (c + 2) : (cEnd - 1);
#pragma unroll
            for (int i = 0; i < 4; ++i) raw[s][i] = pwq[pc * 4 + i];
            sW[wid][lane] = wv;
        }
        __syncwarp();
        uint4 W4[4];
#pragma unroll
        for (int j = 0; j < 4; ++j) W4[j] = sW[wid][rb + 8 * j];

        // compute chunk c from fp16 slot c&1
        const uint32_t bbase = sB0 + (uint32_t)((c & 1) * B16BUF) + nb_off;
#pragma unroll
        for (int ks = 0; ks < 4; ++ks) {
            uint32_t b0, b1, b2, b3, b4, b5, b6, b7;
            ldsm4_nt(bbase + ks * 32,              b0, b1, b2, b3);  // ntiles 0,1
            ldsm4_nt(bbase + 16 * BROWN + ks * 32, b4, b5, b6, b7);  // ntiles 2,3
#pragma unroll
            for (int af = 0; af < 2; ++af) {
                const uint32_t wlo = (&W4[2 * af].x)[ks];
                const uint32_t whi = (&W4[2 * af + 1].x)[ks];
                uint32_t a0, a1, a2, a3;
                dec(wlo, sh, a0, a2);
                dec(whi, sh, a1, a3);
                mma16816(acc[af][0], a0, a1, a2, a3, b0, b1);
                mma16816(acc[af][1], a0, a1, a2, a3, b2, b3);
                mma16816(acc[af][2], a0, a1, a2, a3, b4, b5);
                mma16816(acc[af][3], a0, a1, a2, a3, b6, b7);
            }
        }
    }

    // ---- write fp32 partials for this K-quarter ----
    float* pout = g_part + (size_t)sq * NB * U_DIM;
#pragma unroll
    for (int af = 0; af < 2; ++af) {
        const int ua = u0 + wid * 32 + af * 16 + rb;
        const int ub = ua + 8;
#pragma unroll
        for (int nt = 0; nt < 4; ++nt) {
            const int n0 = nt * 8 + (lane & 3) * 2;
            pout[(size_t)n0 * U_DIM + ua]       = acc[af][nt][0];
            pout[(size_t)(n0 + 1) * U_DIM + ua] = acc[af][nt][1];
            pout[(size_t)n0 * U_DIM + ub]       = acc[af][nt][2];
            pout[(size_t)(n0 + 1) * U_DIM + ub] = acc[af][nt][3];
        }
    }

    // ---- fused split-K reduce: last CTA of this u-tile does scale/bias/clip ----
    __threadfence();
    __syncthreads();
    if (tid == 0) {
        unsigned o = atomicAdd(&g_cnt[bu], 1u);
        sLast = ((o & 3u) == 3u);
    }
    __syncthreads();
    if (sLast) {
        __threadfence();
        const int uu  = u0 + lane * 4;                   // 32 lanes * 4 = 128 u
        const int nb0 = wid * 8;                         // 4 warps * 8 = 32 n
        const float4 sc = *reinterpret_cast<const float4*>(scale + uu);
        const float4 bi = *reinterpret_cast<const float4*>(bias + uu);
#pragma unroll
        for (int e = 0; e < 8; ++e) {
            const size_t i4 = (size_t)(nb0 + e) * U_DIM + uu;
            const float4 p0 = *reinterpret_cast<const float4*>(g_part + i4);
            const float4 p1 = *reinterpret_cast<const float4*>(g_part + (size_t)NB * U_DIM + i4);
            const float4 p2 = *reinterpret_cast<const float4*>(g_part + (size_t)2 * NB * U_DIM + i4);
            const float4 p3 = *reinterpret_cast<const float4*>(g_part + (size_t)3 * NB * U_DIM + i4);
            float4 r;
            r.x = fminf(fmaxf((p0.x + p1.x + p2.x + p3.x) * sc.x + bi.x, -CLIPV), CLIPV);
            r.y = fminf(fmaxf((p0.y + p1.y + p2.y + p3.y) * sc.y + bi.y, -CLIPV), CLIPV);
            r.z = fminf(fmaxf((p0.z + p1.z + p2.z + p3.z) * sc.z + bi.z, -CLIPV), CLIPV);
            r.w = fminf(fmaxf((p0.w + p1.w + p2.w + p3.w) * sc.w + bi.w, -CLIPV), CLIPV);
            *reinterpret_cast<float4*>(out + i4) = r;
        }
    }
}

// ===================== launch =====================
extern "C" void kernel_launch(void* const* d_in, const int* in_sizes, int n_in,
                              void* d_out, int out_size) {
    const float* x     = (const float*)d_in[0];
    const int*   pw    = (const int*)d_in[1];
    const float* scale = (const float*)d_in[2];
    const float* bias  = (const float*)d_in[3];
    float*       out   = (float*)d_out;

    ternary_fused_kernel<<<NCTA_U * NSPLIT, 128>>>(x, pw, scale, bias, out);
}

// round 16
// speedup vs baseline: 1.1298x; 1.1298x over previous
#include <cuda_runtime.h>
#include <cuda_fp16.h>
#include <cstdint>

// ===================== problem constants =====================
#define U_DIM   14336
#define K_DIM   4096
#define NB      32
#define TILE_M  128
#define NCTA_U  (U_DIM / TILE_M)     // 112
#define NCHUNK  (K_DIM / 64)         // 64 chunks of 64 k-values
#define NSPLIT  4
#define NCHUNK_Q (NCHUNK / NSPLIT)   // 16 chunks per CTA
#define CLIPV   100.0f
// PRMT LUT bytes: crumb 0->0x00, 1->0x3C (+1 fp16 hi), 2->0xBC (-1), 3->0x00
#define HI_LUT  0x00BC3C00u

// smem geometry: fp16 B ring [n][k], 128B data + 16B pad per row
#define BROWN   144
#define B16BUF  (32 * BROWN)         // 4608 B per fp16 ring slot

// x as fp16, natural [n][k] layout (written by convert pre-kernel)
__device__ __half  g_xh[NB * K_DIM];
// split-K fp32 partials: [split][n][u]; per-u-tile completion counters
__device__ float    g_part[NSPLIT * NB * U_DIM];
__device__ unsigned g_cnt[NCTA_U];

// ===================== helpers =====================
__device__ __forceinline__ uint32_t prmt(uint32_t a, uint32_t b, uint32_t s) {
    uint32_t r; asm("prmt.b32 %0,%1,%2,%3;" : "=r"(r) : "r"(a), "r"(b), "r"(s)); return r;
}
__device__ __forceinline__ uint32_t smem_u32(const void* p) {
    uint32_t a;
    asm("{ .reg .u64 t; cvta.to.shared.u64 t, %1; cvt.u32.u64 %0, t; }" : "=r"(a) : "l"(p));
    return a;
}
// merge 4 int32 (one crumb-byte each, low byte) -> one 32-bit word of 16 crumbs
__device__ __forceinline__ uint32_t mergew(uint4 q) {
    return prmt(prmt(q.x, q.y, 0x0040), prmt(q.z, q.w, 0x0040), 0x5410);
}
// decode: from 16-crumb word w, lane's quad q (sh=4q): crumbs (2q,2q+1) -> lo,
// crumbs (2q+8,2q+9) -> hi, as fp16x2
__device__ __forceinline__ void dec(uint32_t w, uint32_t sh, uint32_t& lo, uint32_t& hi) {
    uint32_t t   = w >> sh;
    uint32_t x   = t & 0x000F000Fu;
    uint32_t z   = x | (x << 2);
    uint32_t sel = (z & 0x33u) | ((z >> 8) & 0x3300u);
    uint32_t h   = prmt(HI_LUT, 0u, sel);
    lo = prmt(h, 0u, 0x1404u);
    hi = prmt(h, 0u, 0x3424u);
}
__device__ __forceinline__ void mma16816(float* c,
        uint32_t a0, uint32_t a1, uint32_t a2, uint32_t a3,
        uint32_t b0, uint32_t b1) {
    asm volatile(
        "mma.sync.aligned.m16n8k16.row.col.f32.f16.f16.f32 "
        "{%0,%1,%2,%3},{%4,%5,%6,%7},{%8,%9},{%0,%1,%2,%3};"
        : "+f"(c[0]), "+f"(c[1]), "+f"(c[2]), "+f"(c[3])
        : "r"(a0), "r"(a1), "r"(a2), "r"(a3), "r"(b0), "r"(b1));
}
// NON-transposed ldmatrix: B stored [n][k] fp16; 8 n-rows x 16B k-segment per matrix
__device__ __forceinline__ void ldsm4_nt(uint32_t addr,
        uint32_t& r0, uint32_t& r1, uint32_t& r2, uint32_t& r3) {
    asm volatile("ldmatrix.sync.aligned.m8n8.x4.shared.b16 {%0,%1,%2,%3}, [%4];"
        : "=r"(r0), "=r"(r1), "=r"(r2), "=r"(r3) : "r"(addr));
}
__device__ __forceinline__ void cp16(uint32_t saddr, const void* gptr) {
    asm volatile("cp.async.ca.shared.global [%0], [%1], 16;"
                 :: "r"(saddr), "l"(__cvta_generic_to_global(gptr)) : "memory");
}
#define CP_COMMIT() asm volatile("cp.async.commit_group;" ::: "memory")
#define CP_WAIT2()  asm volatile("cp.async.wait_group 2;"  ::: "memory")
// pack 2 fp32 -> fp16x2 {lo, hi}
__device__ __forceinline__ uint32_t f16x2(float lo, float hi) {
    uint32_t r; asm("cvt.rn.f16x2.f32 %0, %1, %2;" : "=r"(r) : "f"(hi), "f"(lo)); return r;
}

// ===================== pre-kernel: pure streaming convert x f32 -> g_xh f16 =====================
// no transpose, no permute; 8 floats per thread; fully coalesced both sides
__global__ void __launch_bounds__(256)
xh_kernel(const float* __restrict__ x) {
    const int t = blockIdx.x * 256 + threadIdx.x;      // 16384 threads
    const float4* src = reinterpret_cast<const float4*>(x) + (size_t)t * 2;
    float4 a = src[0], b = src[1];
    uint4 o;
    o.x = f16x2(a.x, a.y); o.y = f16x2(a.z, a.w);
    o.z = f16x2(b.x, b.y); o.w = f16x2(b.z, b.w);
    reinterpret_cast<uint4*>(g_xh)[t] = o;
}

// ===================== fused GEMM + split-K reduce =====================
// grid 448 x 128 threads, occupancy 4 (one wave on 148 SMs)
// CTA = (u-tile bu, K-quarter sq). B staged fp16 via cp.async (3-deep ring).
__global__ void __launch_bounds__(128, 4)
ternary_fused_kernel(const int*   __restrict__ pw,
                     const float* __restrict__ scale,
                     const float* __restrict__ bias,
                     float*       __restrict__ out) {
    __shared__ __align__(16) uint8_t sB16[4][B16BUF]; // fp16 B ring [n][k] (18432 B)
    __shared__ __align__(16) uint4   sW[4][32];       // per-warp W transpose (2048 B)
    __shared__ int sLast;

    const int tid  = threadIdx.x;
    const int lane = tid & 31;
    const int wid  = tid >> 5;
    const int bu   = blockIdx.x >> 2;        // u-tile    (0..111)
    const int sq   = blockIdx.x & 3;         // K-quarter (0..3)
    const int u0   = bu * TILE_M;
    const int c0   = sq * NCHUNK_Q;          // multiple of 4 -> ring slot = c&3
    const int cEnd = c0 + NCHUNK_Q;
    const uint32_t sh = (lane & 3) * 4;
    const int rb   = lane >> 2;

    // ---- pw stream: lane owns weight row u0 + wid*32 + lane ----
    const int urow = u0 + wid * 32 + lane;
    const uint4* pwq = reinterpret_cast<const uint4*>(pw + (size_t)urow * (K_DIM / 4));

    const uint32_t sB0 = smem_u32(sB16);
    // cp.async staging task: thread t -> n-row = t>>2, 32B segment = t&3
    const int st_n = tid >> 2;
    const int st_s = tid & 3;
    const uint8_t* xhb = reinterpret_cast<const uint8_t*>(g_xh)
                       + (size_t)st_n * (K_DIM * 2) + st_s * 32;   // + c*128 per chunk
    const uint32_t stb = sB0 + (uint32_t)(st_n * BROWN + st_s * 32);
    // ldmatrix per-lane offset within a (ntile-pair, ks) call
    const uint32_t nb_off = (uint32_t)(((lane >> 4) & 1) * (8 * BROWN)
                                       + (lane & 7) * BROWN
                                       + ((lane >> 3) & 1) * 16);

    float acc[2][4][4];
#pragma unroll
    for (int a = 0; a < 2; ++a)
#pragma unroll
        for (int t = 0; t < 4; ++t)
#pragma unroll
            for (int j = 0; j < 4; ++j) acc[a][t][j] = 0.0f;

    // ---- prologue: pw ring depth 2; cp.async-stage B chunks c0..c0+2 ----
    uint4 raw[2][4];
#pragma unroll
    for (int s = 0; s < 2; ++s)
#pragma unroll
        for (int i = 0; i < 4; ++i) raw[s][i] = pwq[(c0 + s) * 4 + i];

#pragma unroll
    for (int cc = 0; cc < 3; ++cc) {
        const uint8_t* g = xhb + (size_t)(c0 + cc) * 128;
        const uint32_t sdst = stb + (uint32_t)(cc * B16BUF);
        cp16(sdst,      g);
        cp16(sdst + 16, g + 16);
        CP_COMMIT();
    }

    // ---- main loop: one __syncthreads per chunk ----
#pragma unroll 4
    for (int c = c0; c < cEnd; ++c) {
        // group for chunk c complete (<=2 outstanding)
        CP_WAIT2();
        // barrier: chunk c data visible to all; previous readers of recycled
        // slot (c+3)&3 (compute of chunk c-1) are done
        __syncthreads();

        // stage chunk c+3 into freed slot (always commit to keep accounting)
        if (c + 3 < cEnd) {
            const uint8_t* g = xhb + (size_t)(c + 3) * 128;
            const uint32_t sdst = stb + (uint32_t)(((c + 3) & 3) * B16BUF);
            cp16(sdst,      g);
            cp16(sdst + 16, g + 16);
        }
        CP_COMMIT();

        // W: merge chunk c, prefetch pw c+2, warp-local transpose via smem
        const int s = c & 1;
        {
            uint4 wv;
            wv.x = mergew(raw[s][0]);
            wv.y = mergew(raw[s][1]);
            wv.z = mergew(raw[s][2]);
            wv.w = mergew(raw[s][3]);
            int pc = (c + 2 < cEnd) ? (c + 2) : (cEnd - 1);
#pragma unroll
            for (int i = 0; i < 4; ++i) raw[s][i] = pwq[pc * 4 + i];
            sW[wid][lane] = wv;
        }
        __syncwarp();
        uint4 W4[4];
#pragma unroll
        for (int j = 0; j < 4; ++j) W4[j] = sW[wid][rb + 8 * j];
        __syncwarp();

        // compute chunk c from fp16 slot c&3
        const uint32_t bbase = sB0 + (uint32_t)((c & 3) * B16BUF) + nb_off;
#pragma unroll
        for (int ks = 0; ks < 4; ++ks) {
            uint32_t b0, b1, b2, b3, b4, b5, b6, b7;
            ldsm4_nt(bbase + ks * 32,              b0, b1, b2, b3);  // ntiles 0,1
            ldsm4_nt(bbase + 16 * BROWN + ks * 32, b4, b5, b6, b7);  // ntiles 2,3
#pragma unroll
            for (int af = 0; af < 2; ++af) {
                const uint32_t wlo = (&W4[2 * af].x)[ks];
                const uint32_t whi = (&W4[2 * af + 1].x)[ks];
                uint32_t a0, a1, a2, a3;
                dec(wlo, sh, a0, a2);
                dec(whi, sh, a1, a3);
                mma16816(acc[af][0], a0, a1, a2, a3, b0, b1);
                mma16816(acc[af][1], a0, a1, a2, a3, b2, b3);
                mma16816(acc[af][2], a0, a1, a2, a3, b4, b5);
                mma16816(acc[af][3], a0, a1, a2, a3, b6, b7);
            }
        }
    }

    // ---- write fp32 partials for this K-quarter ----
    float* pout = g_part + (size_t)sq * NB * U_DIM;
#pragma unroll
    for (int af = 0; af < 2; ++af) {
        const int ua = u0 + wid * 32 + af * 16 + rb;
        const int ub = ua + 8;
#pragma unroll
        for (int nt = 0; nt < 4; ++nt) {
            const int n0 = nt * 8 + (lane & 3) * 2;
            pout[(size_t)n0 * U_DIM + ua]       = acc[af][nt][0];
            pout[(size_t)(n0 + 1) * U_DIM + ua] = acc[af][nt][1];
            pout[(size_t)n0 * U_DIM + ub]       = acc[af][nt][2];
            pout[(size_t)(n0 + 1) * U_DIM + ub] = acc[af][nt][3];
        }
    }

    // ---- fused split-K reduce: last CTA of this u-tile does scale/bias/clip ----
    __threadfence();
    __syncthreads();
    if (tid == 0) {
        unsigned o = atomicAdd(&g_cnt[bu], 1u);
        sLast = ((o & 3u) == 3u);
    }
    __syncthreads();
    if (sLast) {
        __threadfence();
        const int uu  = u0 + lane * 4;                   // 32 lanes * 4 = 128 u
        const int nb0 = wid * 8;                         // 4 warps * 8 = 32 n
        const float4 sc = *reinterpret_cast<const float4*>(scale + uu);
        const float4 bi = *reinterpret_cast<const float4*>(bias + uu);
#pragma unroll
        for (int e = 0; e < 8; ++e) {
            const size_t i4 = (size_t)(nb0 + e) * U_DIM + uu;
            const float4 p0 = *reinterpret_cast<const float4*>(g_part + i4);
            const float4 p1 = *reinterpret_cast<const float4*>(g_part + (size_t)NB * U_DIM + i4);
            const float4 p2 = *reinterpret_cast<const float4*>(g_part + (size_t)2 * NB * U_DIM + i4);
            const float4 p3 = *reinterpret_cast<const float4*>(g_part + (size_t)3 * NB * U_DIM + i4);
            float4 r;
            r.x = fminf(fmaxf((p0.x + p1.x + p2.x + p3.x) * sc.x + bi.x, -CLIPV), CLIPV);
            r.y = fminf(fmaxf((p0.y + p1.y + p2.y + p3.y) * sc.y + bi.y, -CLIPV), CLIPV);
            r.z = fminf(fmaxf((p0.z + p1.z + p2.z + p3.z) * sc.z + bi.z, -CLIPV), CLIPV);
            r.w = fminf(fmaxf((p0.w + p1.w + p2.w + p3.w) * sc.w + bi.w, -CLIPV), CLIPV);
            *reinterpret_cast<float4*>(out + i4) = r;
        }
    }
}

// ===================== launch =====================
extern "C" void kernel_launch(void* const* d_in, const int* in_sizes, int n_in,
                              void* d_out, int out_size) {
    const float* x     = (const float*)d_in[0];
    const int*   pw    = (const int*)d_in[1];
    const float* scale = (const float*)d_in[2];
    const float* bias  = (const float*)d_in[3];
    float*       out   = (float*)d_out;

    xh_kernel<<<(NB * K_DIM) / (256 * 8), 256>>>(x);
    ternary_fused_kernel<<<NCTA_U * NSPLIT, 128>>>(pw, scale, bias, out);
}